// round 6
// baseline (speedup 1.0000x reference)
#include <cuda_runtime.h>

// GraphAppnp: fused sum-aggregation + APPNP alpha blend. HBM-bound streaming.
// Full-CTA co-streaming: one CTA (8 warps, 256 thr) per node; warp w handles
// k-rows [w*4, w*4+4), so the node's entire 8KB region (x3 streams) is swept
// simultaneously by co-scheduled warps -> max DRAM row-buffer locality.
// Within a warp: lanes 0-15 -> even row of pair, lanes 16-31 -> odd row, so
// every warp-level load/store is one 512B fully-contiguous block.
// Inputs: x[N,D], neighbor_agg[N,K,D], h[N,D], neighbor[N,K,D]
// Outputs (concat): x_out[N,D] then nbr_out[N,K,D]
// N=50000, K=32, D=64, ALPHA=0.1

#define ALPHA     0.1f
#define ONE_M_A   0.9f
#define KNBR      32
#define DDIM      64
#define D4        16          // D/4 float4 per row
#define PSTEPS    2           // pair-steps per warp (4 rows = 1/8 of K)

__global__ __launch_bounds__(256, 4)
void appnp_fused_kernel(const float4* __restrict__ x,
                        const float4* __restrict__ nagg,
                        const float4* __restrict__ h,
                        const float4* __restrict__ nbr,
                        float4* __restrict__ out_x,
                        float4* __restrict__ out_nbr,
                        int n_nodes)
{
    __shared__ float4 sacc[8][32];   // [warp][lane] partial sums (4KB)

    int wid   = threadIdx.x >> 5;    // 0..7  k-octant
    int lane  = threadIdx.x & 31;
    int d4    = lane & 15;
    int khalf = lane >> 4;           // 0: even row of pair, 1: odd row

    int node = blockIdx.x;
    if (node >= n_nodes) return;

    // warp base: (node, row = wid*4 + khalf, float4 d4); pair-step stride = 2 rows
    size_t row_base = (size_t)node * (KNBR * D4)
                    + (size_t)(wid * 4 + khalf) * D4 + d4;
    const float4* na_p  = nagg    + row_base;
    const float4* nb_p  = nbr     + row_base;
    float4*       out_p = out_nbr + row_base;

    size_t xr = (size_t)node * D4 + d4;
    float4 xv = x[xr];

    float4 a[PSTEPS], b[PSTEPS];

    #pragma unroll
    for (int j = 0; j < PSTEPS; ++j) {
        size_t off = (size_t)j * (2 * D4);
        a[j] = __ldcs(na_p + off);       // 512B contiguous per warp
        b[j] = __ldcs(nb_p + off);
    }

    float4 acc = make_float4(0.f, 0.f, 0.f, 0.f);

    #pragma unroll
    for (int j = 0; j < PSTEPS; ++j) {
        acc.x += a[j].x; acc.y += a[j].y; acc.z += a[j].z; acc.w += a[j].w;
        b[j].x = fmaf(ONE_M_A, a[j].x + xv.x, ALPHA * b[j].x);
        b[j].y = fmaf(ONE_M_A, a[j].y + xv.y, ALPHA * b[j].y);
        b[j].z = fmaf(ONE_M_A, a[j].z + xv.z, ALPHA * b[j].z);
        b[j].w = fmaf(ONE_M_A, a[j].w + xv.w, ALPHA * b[j].w);
    }

    #pragma unroll
    for (int j = 0; j < PSTEPS; ++j) {
        size_t off = (size_t)j * (2 * D4);
        __stcs(out_p + off, b[j]);       // 512B contiguous per warp
    }

    // cross-warp reduction of the per-node neighbor sum
    sacc[wid][lane] = acc;
    __syncthreads();

    // warp 0, lanes 0-15 finalize the node's x_out row
    if (wid == 0 && lane < 16) {
        float4 s = make_float4(0.f, 0.f, 0.f, 0.f);
        #pragma unroll
        for (int j = 0; j < 8; ++j) {
            float4 v0 = sacc[j][lane];
            float4 v1 = sacc[j][lane + 16];
            s.x += v0.x + v1.x; s.y += v0.y + v1.y;
            s.z += v0.z + v1.z; s.w += v0.w + v1.w;
        }
        float4 hv = h[xr];
        float4 xo;
        xo.x = fmaf(ONE_M_A, xv.x + s.x, ALPHA * hv.x);
        xo.y = fmaf(ONE_M_A, xv.y + s.y, ALPHA * hv.y);
        xo.z = fmaf(ONE_M_A, xv.z + s.z, ALPHA * hv.z);
        xo.w = fmaf(ONE_M_A, xv.w + s.w, ALPHA * hv.w);
        out_x[xr] = xo;
    }
}

extern "C" void kernel_launch(void* const* d_in, const int* in_sizes, int n_in,
                              void* d_out, int out_size)
{
    const float4* x    = (const float4*)d_in[0];
    const float4* nagg = (const float4*)d_in[1];
    const float4* h    = (const float4*)d_in[2];
    const float4* nbr  = (const float4*)d_in[3];

    int n_nodes = in_sizes[0] / DDIM;

    float4* out_x   = (float4*)d_out;
    float4* out_nbr = (float4*)d_out + (size_t)n_nodes * D4;

    appnp_fused_kernel<<<n_nodes, 256>>>(x, nagg, h, nbr, out_x, out_nbr, n_nodes);
}

// round 7
// speedup vs baseline: 1.0562x; 1.0562x over previous
#include <cuda_runtime.h>
#include <cstdint>

// GraphAppnp: fused sum-aggregation + APPNP alpha blend. HBM-bound streaming.
// R5 read layout (proven best): CTA=256thr handles 2 nodes; 4 warps co-stream
// one node's 8KB region; warp-level loads are 512B fully contiguous; PSTEPS=4
// keeps 16 outstanding loads/thread.
// NEW: nbr_out is staged in smem and written as ONE 8KB cp.async.bulk S2G
// store per node -> each node's output reaches DRAM as a single sequential
// bulk write burst issued by the TMA engine.
// Inputs: x[N,D], neighbor_agg[N,K,D], h[N,D], neighbor[N,K,D]
// Outputs (concat): x_out[N,D] then nbr_out[N,K,D]
// N=50000, K=32, D=64, ALPHA=0.1

#define ALPHA     0.1f
#define ONE_M_A   0.9f
#define KNBR      32
#define DDIM      64
#define D4        16          // D/4 float4 per row
#define PSTEPS    4           // pair-steps per warp (8 rows = quarter of K)

__device__ __forceinline__ uint32_t smem_u32(const void* p) {
    return (uint32_t)__cvta_generic_to_shared(p);
}

__global__ __launch_bounds__(256, 3)
void appnp_fused_kernel(const float4* __restrict__ x,
                        const float4* __restrict__ nagg,
                        const float4* __restrict__ h,
                        const float4* __restrict__ nbr,
                        float4* __restrict__ out_x,
                        float4* __restrict__ out_nbr,
                        int n_nodes)
{
    __shared__ float4 souts[2][KNBR][D4];  // staged output tiles, 2 x 8KB
    __shared__ float4 sacc[8][32];         // [warp][lane] partial sums (4KB)

    int wid   = threadIdx.x >> 5;    // 0..7
    int lane  = threadIdx.x & 31;
    int d4    = lane & 15;
    int khalf = lane >> 4;           // 0: even row of pair, 1: odd row
    int nloc  = wid >> 2;            // 0..1  node within CTA
    int kq    = wid & 3;             // 0..3  k-quarter within node

    int node = blockIdx.x * 2 + nloc;
    if (node >= n_nodes) return;     // n_nodes even (50000): whole CTA uniform

    // warp base: (node, row = kq*8 + khalf, float4 d4); pair-step stride = 2 rows
    size_t row_base = (size_t)node * (KNBR * D4)
                    + (size_t)(kq * 8 + khalf) * D4 + d4;
    const float4* na_p = nagg + row_base;
    const float4* nb_p = nbr  + row_base;

    size_t xr = (size_t)node * D4 + d4;
    float4 xv = x[xr];

    float4 a[PSTEPS], b[PSTEPS];

    #pragma unroll
    for (int j = 0; j < PSTEPS; ++j) {
        size_t off = (size_t)j * (2 * D4);
        a[j] = __ldcs(na_p + off);       // 512B contiguous per warp
        b[j] = __ldcs(nb_p + off);
    }

    float4 acc = make_float4(0.f, 0.f, 0.f, 0.f);

    #pragma unroll
    for (int j = 0; j < PSTEPS; ++j) {
        acc.x += a[j].x; acc.y += a[j].y; acc.z += a[j].z; acc.w += a[j].w;
        b[j].x = fmaf(ONE_M_A, a[j].x + xv.x, ALPHA * b[j].x);
        b[j].y = fmaf(ONE_M_A, a[j].y + xv.y, ALPHA * b[j].y);
        b[j].z = fmaf(ONE_M_A, a[j].z + xv.z, ALPHA * b[j].z);
        b[j].w = fmaf(ONE_M_A, a[j].w + xv.w, ALPHA * b[j].w);
    }

    // stage output tile in smem (conflict-free: 16 lanes x 16B consecutive)
    #pragma unroll
    for (int j = 0; j < PSTEPS; ++j) {
        int row = kq * 8 + j * 2 + khalf;
        souts[nloc][row][d4] = b[j];
    }

    sacc[wid][lane] = acc;

    // make STS visible to the async proxy, then sync the CTA
    asm volatile("fence.proxy.async.shared::cta;" ::: "memory");
    __syncthreads();

    // one elected thread per node issues the 8KB bulk store
    if (lane == 0 && kq == 0) {
        float4* dst = out_nbr + (size_t)node * (KNBR * D4);
        uint32_t src = smem_u32(&souts[nloc][0][0]);
        asm volatile(
            "cp.async.bulk.global.shared::cta.bulk_group [%0], [%1], %2;"
            :: "l"(dst), "r"(src), "n"(KNBR * D4 * 16) : "memory");
        asm volatile("cp.async.bulk.commit_group;" ::: "memory");
    }

    // warps 0,1 finalize x_out for nodes 0,1 (lanes 0-15)
    if (wid < 2 && lane < 16) {
        int nl = wid;
        float4 s = make_float4(0.f, 0.f, 0.f, 0.f);
        #pragma unroll
        for (int j = 0; j < 4; ++j) {
            float4 v0 = sacc[nl * 4 + j][lane];
            float4 v1 = sacc[nl * 4 + j][lane + 16];
            s.x += v0.x + v1.x; s.y += v0.y + v1.y;
            s.z += v0.z + v1.z; s.w += v0.w + v1.w;
        }
        int fnode = blockIdx.x * 2 + nl;
        size_t fr = (size_t)fnode * D4 + lane;
        float4 xf = x[fr];
        float4 hv = h[fr];
        float4 xo;
        xo.x = fmaf(ONE_M_A, xf.x + s.x, ALPHA * hv.x);
        xo.y = fmaf(ONE_M_A, xf.y + s.y, ALPHA * hv.y);
        xo.z = fmaf(ONE_M_A, xf.z + s.z, ALPHA * hv.z);
        xo.w = fmaf(ONE_M_A, xf.w + s.w, ALPHA * hv.w);
        out_x[fr] = xo;
    }

    // smem must stay valid until the bulk store has read it
    if (lane == 0 && kq == 0) {
        asm volatile("cp.async.bulk.wait_group.read 0;" ::: "memory");
    }
    __syncthreads();
}

extern "C" void kernel_launch(void* const* d_in, const int* in_sizes, int n_in,
                              void* d_out, int out_size)
{
    const float4* x    = (const float4*)d_in[0];
    const float4* nagg = (const float4*)d_in[1];
    const float4* h    = (const float4*)d_in[2];
    const float4* nbr  = (const float4*)d_in[3];

    int n_nodes = in_sizes[0] / DDIM;

    float4* out_x   = (float4*)d_out;
    float4* out_nbr = (float4*)d_out + (size_t)n_nodes * D4;

    int grid = (n_nodes + 1) / 2;    // 2 nodes per CTA

    appnp_fused_kernel<<<grid, 256>>>(x, nagg, h, nbr, out_x, out_nbr, n_nodes);
}

// round 8
// speedup vs baseline: 1.0592x; 1.0028x over previous
#include <cuda_runtime.h>

// GraphAppnp: fused sum-aggregation + APPNP alpha blend. HBM-bound streaming.
// R5 layout (best): CTA=256thr handles 2 nodes; 4 warps co-stream one node's
// 8KB region (warp w: node w/4, k-quarter w%4); lanes 0-15 even row / 16-31
// odd row -> every warp load/store is one 512B fully-contiguous block.
// R8 delta: stores use __stwt (write-through streaming) so the never-re-read
// 432MB output stream doesn't allocate/displace lines in L2.
// Inputs: x[N,D], neighbor_agg[N,K,D], h[N,D], neighbor[N,K,D]
// Outputs (concat): x_out[N,D] then nbr_out[N,K,D]
// N=50000, K=32, D=64, ALPHA=0.1

#define ALPHA     0.1f
#define ONE_M_A   0.9f
#define KNBR      32
#define DDIM      64
#define D4        16          // D/4 float4 per row
#define PSTEPS    4           // pair-steps per warp (8 rows = quarter of K)

__global__ __launch_bounds__(256, 3)
void appnp_fused_kernel(const float4* __restrict__ x,
                        const float4* __restrict__ nagg,
                        const float4* __restrict__ h,
                        const float4* __restrict__ nbr,
                        float4* __restrict__ out_x,
                        float4* __restrict__ out_nbr,
                        int n_nodes)
{
    __shared__ float4 sacc[8][32];   // [warp][lane] partial sums (4KB)

    int wid   = threadIdx.x >> 5;    // 0..7
    int lane  = threadIdx.x & 31;
    int d4    = lane & 15;
    int khalf = lane >> 4;           // 0: even row of pair, 1: odd row
    int nloc  = wid >> 2;            // 0..1  node within CTA
    int kq    = wid & 3;             // 0..3  k-quarter within node

    int node = blockIdx.x * 2 + nloc;
    if (node >= n_nodes) return;     // n_nodes even (50000), whole CTA exits

    // warp base: (node, row = kq*8 + khalf, float4 d4); pair-step stride = 2 rows
    size_t row_base = (size_t)node * (KNBR * D4)
                    + (size_t)(kq * 8 + khalf) * D4 + d4;
    const float4* na_p  = nagg    + row_base;
    const float4* nb_p  = nbr     + row_base;
    float4*       out_p = out_nbr + row_base;

    size_t xr = (size_t)node * D4 + d4;
    float4 xv = x[xr];

    float4 a[PSTEPS], b[PSTEPS];

    #pragma unroll
    for (int j = 0; j < PSTEPS; ++j) {
        size_t off = (size_t)j * (2 * D4);
        a[j] = __ldcs(na_p + off);       // 512B contiguous per warp
        b[j] = __ldcs(nb_p + off);
    }

    float4 acc = make_float4(0.f, 0.f, 0.f, 0.f);

    #pragma unroll
    for (int j = 0; j < PSTEPS; ++j) {
        acc.x += a[j].x; acc.y += a[j].y; acc.z += a[j].z; acc.w += a[j].w;
        b[j].x = fmaf(ONE_M_A, a[j].x + xv.x, ALPHA * b[j].x);
        b[j].y = fmaf(ONE_M_A, a[j].y + xv.y, ALPHA * b[j].y);
        b[j].z = fmaf(ONE_M_A, a[j].z + xv.z, ALPHA * b[j].z);
        b[j].w = fmaf(ONE_M_A, a[j].w + xv.w, ALPHA * b[j].w);
    }

    #pragma unroll
    for (int j = 0; j < PSTEPS; ++j) {
        size_t off = (size_t)j * (2 * D4);
        __stwt(out_p + off, b[j]);       // write-through: no L2 allocation
    }

    // cross-warp reduction of the per-node neighbor sum
    sacc[wid][lane] = acc;
    __syncthreads();

    // warp 0 finalizes node 0, warp 1 finalizes node 1 (lanes 0-15 active)
    if (wid < 2 && lane < 16) {
        int nl = wid;
        float4 s = make_float4(0.f, 0.f, 0.f, 0.f);
        #pragma unroll
        for (int j = 0; j < 4; ++j) {
            float4 v0 = sacc[nl * 4 + j][lane];
            float4 v1 = sacc[nl * 4 + j][lane + 16];
            s.x += v0.x + v1.x; s.y += v0.y + v1.y;
            s.z += v0.z + v1.z; s.w += v0.w + v1.w;
        }
        int fnode = blockIdx.x * 2 + nl;
        size_t fr = (size_t)fnode * D4 + lane;
        float4 xf = x[fr];
        float4 hv = h[fr];
        float4 xo;
        xo.x = fmaf(ONE_M_A, xf.x + s.x, ALPHA * hv.x);
        xo.y = fmaf(ONE_M_A, xf.y + s.y, ALPHA * hv.y);
        xo.z = fmaf(ONE_M_A, xf.z + s.z, ALPHA * hv.z);
        xo.w = fmaf(ONE_M_A, xf.w + s.w, ALPHA * hv.w);
        __stwt(&out_x[fr], xo);
    }
}

extern "C" void kernel_launch(void* const* d_in, const int* in_sizes, int n_in,
                              void* d_out, int out_size)
{
    const float4* x    = (const float4*)d_in[0];
    const float4* nagg = (const float4*)d_in[1];
    const float4* h    = (const float4*)d_in[2];
    const float4* nbr  = (const float4*)d_in[3];

    int n_nodes = in_sizes[0] / DDIM;

    float4* out_x   = (float4*)d_out;
    float4* out_nbr = (float4*)d_out + (size_t)n_nodes * D4;

    int grid = (n_nodes + 1) / 2;    // 2 nodes per CTA

    appnp_fused_kernel<<<grid, 256>>>(x, nagg, h, nbr, out_x, out_nbr, n_nodes);
}

// round 9
// speedup vs baseline: 1.0662x; 1.0067x over previous
#include <cuda_runtime.h>

// GraphAppnp: fused sum-aggregation + APPNP alpha blend. HBM-bound streaming.
// R5 layout (best): CTA=256thr handles 2 nodes; 4 warps co-stream one node's
// 8KB region (warp w: node w/4, k-quarter w%4); lanes 0-15 even row / 16-31
// odd row -> every warp load/store is one 512B fully-contiguous block.
// R9 delta: inner work split into two half-batches (2 pair-steps each) to cut
// register live-ranges (more resident CTAs) and stagger load/store phases.
// Inputs: x[N,D], neighbor_agg[N,K,D], h[N,D], neighbor[N,K,D]
// Outputs (concat): x_out[N,D] then nbr_out[N,K,D]
// N=50000, K=32, D=64, ALPHA=0.1

#define ALPHA     0.1f
#define ONE_M_A   0.9f
#define KNBR      32
#define DDIM      64
#define D4        16          // D/4 float4 per row
#define HB        2           // pair-steps per half-batch
#define NHB       2           // half-batches (total 4 pair-steps = 8 rows/warp)

__global__ __launch_bounds__(256)
void appnp_fused_kernel(const float4* __restrict__ x,
                        const float4* __restrict__ nagg,
                        const float4* __restrict__ h,
                        const float4* __restrict__ nbr,
                        float4* __restrict__ out_x,
                        float4* __restrict__ out_nbr,
                        int n_nodes)
{
    __shared__ float4 sacc[8][32];   // [warp][lane] partial sums (4KB)

    int wid   = threadIdx.x >> 5;    // 0..7
    int lane  = threadIdx.x & 31;
    int d4    = lane & 15;
    int khalf = lane >> 4;           // 0: even row of pair, 1: odd row
    int nloc  = wid >> 2;            // 0..1  node within CTA
    int kq    = wid & 3;             // 0..3  k-quarter within node

    int node = blockIdx.x * 2 + nloc;
    if (node >= n_nodes) return;     // n_nodes even (50000), whole CTA exits

    // warp base: (node, row = kq*8 + khalf, float4 d4); pair-step stride = 2 rows
    size_t row_base = (size_t)node * (KNBR * D4)
                    + (size_t)(kq * 8 + khalf) * D4 + d4;
    const float4* na_p  = nagg    + row_base;
    const float4* nb_p  = nbr     + row_base;
    float4*       out_p = out_nbr + row_base;

    size_t xr = (size_t)node * D4 + d4;
    float4 xv = x[xr];

    float4 acc = make_float4(0.f, 0.f, 0.f, 0.f);

    // software pipeline: prefetch half-batch 0
    float4 a[HB], b[HB];
    #pragma unroll
    for (int j = 0; j < HB; ++j) {
        size_t off = (size_t)j * (2 * D4);
        a[j] = __ldcs(na_p + off);
        b[j] = __ldcs(nb_p + off);
    }

    #pragma unroll
    for (int hb = 0; hb < NHB; ++hb) {
        float4 an[HB], bn[HB];
        if (hb + 1 < NHB) {
            #pragma unroll
            for (int j = 0; j < HB; ++j) {
                size_t off = (size_t)((hb + 1) * HB + j) * (2 * D4);
                an[j] = __ldcs(na_p + off);
                bn[j] = __ldcs(nb_p + off);
            }
        }

        #pragma unroll
        for (int j = 0; j < HB; ++j) {
            acc.x += a[j].x; acc.y += a[j].y; acc.z += a[j].z; acc.w += a[j].w;
            b[j].x = fmaf(ONE_M_A, a[j].x + xv.x, ALPHA * b[j].x);
            b[j].y = fmaf(ONE_M_A, a[j].y + xv.y, ALPHA * b[j].y);
            b[j].z = fmaf(ONE_M_A, a[j].z + xv.z, ALPHA * b[j].z);
            b[j].w = fmaf(ONE_M_A, a[j].w + xv.w, ALPHA * b[j].w);
        }

        #pragma unroll
        for (int j = 0; j < HB; ++j) {
            size_t off = (size_t)(hb * HB + j) * (2 * D4);
            __stcs(out_p + off, b[j]);   // 512B contiguous per warp
        }

        #pragma unroll
        for (int j = 0; j < HB; ++j) { a[j] = an[j]; b[j] = bn[j]; }
    }

    // cross-warp reduction of the per-node neighbor sum
    sacc[wid][lane] = acc;
    __syncthreads();

    // warp 0 finalizes node 0, warp 1 finalizes node 1 (lanes 0-15 active)
    if (wid < 2 && lane < 16) {
        int nl = wid;
        float4 s = make_float4(0.f, 0.f, 0.f, 0.f);
        #pragma unroll
        for (int j = 0; j < 4; ++j) {
            float4 v0 = sacc[nl * 4 + j][lane];
            float4 v1 = sacc[nl * 4 + j][lane + 16];
            s.x += v0.x + v1.x; s.y += v0.y + v1.y;
            s.z += v0.z + v1.z; s.w += v0.w + v1.w;
        }
        int fnode = blockIdx.x * 2 + nl;
        size_t fr = (size_t)fnode * D4 + lane;
        float4 xf = x[fr];
        float4 hv = h[fr];
        float4 xo;
        xo.x = fmaf(ONE_M_A, xf.x + s.x, ALPHA * hv.x);
        xo.y = fmaf(ONE_M_A, xf.y + s.y, ALPHA * hv.y);
        xo.z = fmaf(ONE_M_A, xf.z + s.z, ALPHA * hv.z);
        xo.w = fmaf(ONE_M_A, xf.w + s.w, ALPHA * hv.w);
        out_x[fr] = xo;
    }
}

extern "C" void kernel_launch(void* const* d_in, const int* in_sizes, int n_in,
                              void* d_out, int out_size)
{
    const float4* x    = (const float4*)d_in[0];
    const float4* nagg = (const float4*)d_in[1];
    const float4* h    = (const float4*)d_in[2];
    const float4* nbr  = (const float4*)d_in[3];

    int n_nodes = in_sizes[0] / DDIM;

    float4* out_x   = (float4*)d_out;
    float4* out_nbr = (float4*)d_out + (size_t)n_nodes * D4;

    int grid = (n_nodes + 1) / 2;    // 2 nodes per CTA

    appnp_fused_kernel<<<grid, 256>>>(x, nagg, h, nbr, out_x, out_nbr, n_nodes);
}

// round 10
// speedup vs baseline: 1.0772x; 1.0103x over previous
#include <cuda_runtime.h>

// GraphAppnp: fused sum-aggregation + APPNP alpha blend. HBM-bound streaming.
// R10: 256-bit (v8.f32) loads/stores -> every warp memory instruction is one
// 1KB fully-contiguous block. 4 warps co-stream one node's 8KB region
// (warp w: node w/4, k-quarter w%4); lane l covers 32B, so one v8 instr
// covers 4 k-rows; each warp: 2 v8-loads per stream + 2 v8-stores.
// Inputs: x[N,D], neighbor_agg[N,K,D], h[N,D], neighbor[N,K,D]
// Outputs (concat): x_out[N,D] then nbr_out[N,K,D]
// N=50000, K=32, D=64, ALPHA=0.1

#define ALPHA     0.1f
#define ONE_M_A   0.9f
#define KNBR      32
#define DDIM      64
#define ROWF      64          // floats per row
#define NODEF     (KNBR * ROWF)  // 2048 floats per node region

__device__ __forceinline__ void ldg_cs_v8(const float* p, float* v) {
    asm("ld.global.cs.v8.f32 {%0,%1,%2,%3,%4,%5,%6,%7}, [%8];"
        : "=f"(v[0]), "=f"(v[1]), "=f"(v[2]), "=f"(v[3]),
          "=f"(v[4]), "=f"(v[5]), "=f"(v[6]), "=f"(v[7])
        : "l"(p));
}

__device__ __forceinline__ void ldg_v8(const float* p, float* v) {
    asm("ld.global.v8.f32 {%0,%1,%2,%3,%4,%5,%6,%7}, [%8];"
        : "=f"(v[0]), "=f"(v[1]), "=f"(v[2]), "=f"(v[3]),
          "=f"(v[4]), "=f"(v[5]), "=f"(v[6]), "=f"(v[7])
        : "l"(p));
}

__device__ __forceinline__ void stg_cs_v8(float* p, const float* v) {
    asm volatile("st.global.cs.v8.f32 [%0], {%1,%2,%3,%4,%5,%6,%7,%8};"
        :: "l"(p),
           "f"(v[0]), "f"(v[1]), "f"(v[2]), "f"(v[3]),
           "f"(v[4]), "f"(v[5]), "f"(v[6]), "f"(v[7])
        : "memory");
}

__global__ __launch_bounds__(256)
void appnp_fused_kernel(const float* __restrict__ x,
                        const float* __restrict__ nagg,
                        const float* __restrict__ h,
                        const float* __restrict__ nbr,
                        float* __restrict__ out_x,
                        float* __restrict__ out_nbr,
                        int n_nodes)
{
    __shared__ float4 sacc4[8][16];  // [warp][float4-d-index] partial sums (2KB)

    int wid  = threadIdx.x >> 5;     // 0..7
    int lane = threadIdx.x & 31;
    int nloc = wid >> 2;             // 0..1  node within CTA
    int kq   = wid & 3;              // 0..3  k-quarter within node
    int d8   = lane & 7;             // which 8-float d-slice this lane owns

    int node = blockIdx.x * 2 + nloc;
    if (node >= n_nodes) return;     // n_nodes even (50000), whole CTA uniform

    // warp covers rows [kq*8, kq*8+8); v8 instr j covers rows kq*8+j*4..+4
    // lane l handles bytes [32l, 32l+32) of each 1KB block
    size_t base = (size_t)node * NODEF + (size_t)kq * (8 * ROWF) + (size_t)lane * 8;
    const float* na_p  = nagg    + base;
    const float* nb_p  = nbr     + base;
    float*       out_p = out_nbr + base;

    // x d-slice for this lane (shared by the 4 rows the lane touches)
    const float* xp = x + (size_t)node * ROWF + (size_t)d8 * 8;
    float xv[8];
    ldg_v8(xp, xv);

    float a0[8], a1[8], b0[8], b1[8];
    ldg_cs_v8(na_p,             a0);   // 1KB contiguous per warp instr
    ldg_cs_v8(na_p + 4 * ROWF,  a1);
    ldg_cs_v8(nb_p,             b0);
    ldg_cs_v8(nb_p + 4 * ROWF,  b1);

    float acc[8];
    #pragma unroll
    for (int i = 0; i < 8; ++i) {
        acc[i] = a0[i] + a1[i];
        b0[i] = fmaf(ONE_M_A, a0[i] + xv[i], ALPHA * b0[i]);
        b1[i] = fmaf(ONE_M_A, a1[i] + xv[i], ALPHA * b1[i]);
    }

    stg_cs_v8(out_p,            b0);   // 1KB contiguous per warp instr
    stg_cs_v8(out_p + 4 * ROWF, b1);

    // reduce acc across the 4 lanes sharing this d-slice (l, l^8, l^16, l^24)
    #pragma unroll
    for (int i = 0; i < 8; ++i) {
        acc[i] += __shfl_xor_sync(0xffffffffu, acc[i], 8);
        acc[i] += __shfl_xor_sync(0xffffffffu, acc[i], 16);
    }

    if (lane < 8) {
        sacc4[wid][lane * 2]     = make_float4(acc[0], acc[1], acc[2], acc[3]);
        sacc4[wid][lane * 2 + 1] = make_float4(acc[4], acc[5], acc[6], acc[7]);
    }
    __syncthreads();

    // warp 0 finalizes node 0, warp 1 finalizes node 1 (lanes 0-15 active)
    if (wid < 2 && lane < 16) {
        int nl = wid;
        float4 s = make_float4(0.f, 0.f, 0.f, 0.f);
        #pragma unroll
        for (int j = 0; j < 4; ++j) {
            float4 v = sacc4[nl * 4 + j][lane];
            s.x += v.x; s.y += v.y; s.z += v.z; s.w += v.w;
        }
        int fnode = blockIdx.x * 2 + nl;
        size_t fr = (size_t)fnode * ROWF + (size_t)lane * 4;
        const float4* xf4 = (const float4*)(x + fr);
        const float4* hv4 = (const float4*)(h + fr);
        float4 xf = *xf4;
        float4 hv = *hv4;
        float4 xo;
        xo.x = fmaf(ONE_M_A, xf.x + s.x, ALPHA * hv.x);
        xo.y = fmaf(ONE_M_A, xf.y + s.y, ALPHA * hv.y);
        xo.z = fmaf(ONE_M_A, xf.z + s.z, ALPHA * hv.z);
        xo.w = fmaf(ONE_M_A, xf.w + s.w, ALPHA * hv.w);
        *(float4*)(out_x + fr) = xo;
    }
}

extern "C" void kernel_launch(void* const* d_in, const int* in_sizes, int n_in,
                              void* d_out, int out_size)
{
    const float* x    = (const float*)d_in[0];
    const float* nagg = (const float*)d_in[1];
    const float* h    = (const float*)d_in[2];
    const float* nbr  = (const float*)d_in[3];

    int n_nodes = in_sizes[0] / DDIM;

    float* out_x   = (float*)d_out;
    float* out_nbr = (float*)d_out + (size_t)n_nodes * DDIM;

    int grid = (n_nodes + 1) / 2;    // 2 nodes per CTA

    appnp_fused_kernel<<<grid, 256>>>(x, nagg, h, nbr, out_x, out_nbr, n_nodes);
}